// round 13
// baseline (speedup 1.0000x reference)
#include <cuda_runtime.h>
#include <cstdint>
#include <cstddef>

// out[m] = x[m] @ w[sel[m]]   M=262144, K=64, N=64, E=8, fp32
//
// Strategy:
//  - 152 CTAs (one per SM), 256 threads each, contiguous token range per CTA.
//  - Stage all 8 expert matrices (128 KB) in dynamic shared memory.
//  - CTA-local counting sort of tokens by expert (histogram -> scan -> scatter
//    into u16 index list) so each 32-token warp chunk has ONE expert:
//    all weight reads become warp-uniform smem broadcasts (conflict-free).
//  - Inner product with packed fp32x2 FMA (fma.rn.f32x2): 2 FMAs/instr,
//    halving the FFMA issue cost vs scalar FFMA.

#define TOK_M   262144
#define NCTA    152
#define NTHR    256
#define MAXTB   1760          // ceil(262144/152)=1725, padded

#define SMEM_W_BYTES   (8 * 64 * 64 * 4)            // 131072
#define SMEM_IDX_OFF   SMEM_W_BYTES                 // u16[MAXTB] = 3520 B
#define SMEM_SEL_OFF   (SMEM_IDX_OFF + MAXTB * 2)   // u8[MAXTB]  = 1760 B
#define SMEM_META_OFF  ((SMEM_SEL_OFF + MAXTB + 15) & ~15)
#define SMEM_TOTAL     (SMEM_META_OFF + 160)        // counts/offs/cursor/chunkoff

static __device__ __forceinline__ uint32_t s2u(const void* p) {
    uint32_t a;
    asm("{ .reg .u64 t; cvta.to.shared.u64 t, %1; cvt.u32.u64 %0, t; }"
        : "=r"(a) : "l"(p));
    return a;
}

__global__ void __launch_bounds__(NTHR, 1)
cvmm_kernel(const float* __restrict__ x, const int* __restrict__ sel,
            const float* __restrict__ w, float* __restrict__ out)
{
    extern __shared__ char smem[];
    float*          w_s      = (float*)smem;
    unsigned short* idx      = (unsigned short*)(smem + SMEM_IDX_OFF);
    unsigned char*  sel_s    = (unsigned char*)(smem + SMEM_SEL_OFF);
    int*            counts   = (int*)(smem + SMEM_META_OFF);
    int*            offs     = counts + 8;
    int*            cursor   = offs + 8;
    int*            chunkoff = cursor + 8;   // 9 entries

    const int tid = threadIdx.x;
    const int bid = blockIdx.x;
    const int t0 = (int)(((long long)bid       * TOK_M) / NCTA);
    const int t1 = (int)(((long long)(bid + 1) * TOK_M) / NCTA);
    const int TB = t1 - t0;

    if (tid < 8) counts[tid] = 0;

    // ---- stage all expert weights into smem (coalesced float4 copy) ----
    {
        const float4* wg = (const float4*)w;
        float4*       ws = (float4*)w_s;
        #pragma unroll
        for (int i = 0; i < (SMEM_W_BYTES / 16) / NTHR; i++)
            ws[tid + i * NTHR] = wg[tid + i * NTHR];
    }
    __syncthreads();

    // ---- histogram over experts; stage sel in smem ----
    for (int i = tid; i < TB; i += NTHR) {
        int e = sel[t0 + i] & 7;
        sel_s[i] = (unsigned char)e;
        atomicAdd(&counts[e], 1);
    }
    __syncthreads();

    // ---- exclusive scan + chunk offsets (serial, 8 entries) ----
    if (tid == 0) {
        int acc = 0, cacc = 0;
        #pragma unroll
        for (int e = 0; e < 8; e++) {
            offs[e]     = acc;
            cursor[e]   = acc;
            chunkoff[e] = cacc;
            int c = counts[e];
            acc  += c;
            cacc += (c + 31) >> 5;
        }
        chunkoff[8] = cacc;
    }
    __syncthreads();

    // ---- scatter token local indices into per-expert lists ----
    for (int i = tid; i < TB; i += NTHR) {
        int e = sel_s[i];
        int p = atomicAdd(&cursor[e], 1);
        idx[p] = (unsigned short)i;
    }
    __syncthreads();

    // ---- phase 2: each warp consumes 32-token single-expert chunks ----
    const int nchunks = chunkoff[8];
    const int warp = tid >> 5, lane = tid & 31;
    const uint32_t wsb = s2u(w_s);

    for (int c = warp; c < nchunks; c += NTHR / 32) {
        // find expert owning chunk c (monotone chunkoff; highest match wins,
        // which correctly skips zero-count experts)
        int e = 0;
        #pragma unroll
        for (int q = 1; q < 8; q++)
            if (chunkoff[q] <= c) e = q;

        const int cc     = c - chunkoff[e];
        const int cnt    = counts[e];
        const int nvalid = min(32, cnt - cc * 32);
        const int li     = cc * 32 + (lane < nvalid ? lane : 0);
        const int t      = t0 + (int)idx[offs[e] + li];

        const float4* __restrict__ xrow = (const float4*)(x + (size_t)t * 64);

        unsigned long long acc2[32];
        #pragma unroll
        for (int j = 0; j < 32; j++) acc2[j] = 0ull;

        const uint32_t webase = wsb + (uint32_t)e * 16384u;

        for (int kb = 0; kb < 4; kb++) {         // K in blocks of 16
            float4 xv0 = xrow[kb * 4 + 0];
            float4 xv1 = xrow[kb * 4 + 1];
            float4 xv2 = xrow[kb * 4 + 2];
            float4 xv3 = xrow[kb * 4 + 3];
            float xr[16] = { xv0.x, xv0.y, xv0.z, xv0.w,
                             xv1.x, xv1.y, xv1.z, xv1.w,
                             xv2.x, xv2.y, xv2.z, xv2.w,
                             xv3.x, xv3.y, xv3.z, xv3.w };
            const uint32_t kbase = webase + (uint32_t)kb * 4096u;
            #pragma unroll
            for (int k2 = 0; k2 < 16; k2++) {
                unsigned long long xk2;
                asm("mov.b64 %0, {%1, %1};" : "=l"(xk2) : "f"(xr[k2]));
                const uint32_t a = kbase + (uint32_t)k2 * 256u;
                #pragma unroll
                for (int j = 0; j < 16; j++) {
                    unsigned long long w0, w1;
                    asm volatile("ld.shared.v2.b64 {%0, %1}, [%2];"
                                 : "=l"(w0), "=l"(w1) : "r"(a + j * 16));
                    asm("fma.rn.f32x2 %0, %1, %2, %0;"
                        : "+l"(acc2[2 * j])     : "l"(xk2), "l"(w0));
                    asm("fma.rn.f32x2 %0, %1, %2, %0;"
                        : "+l"(acc2[2 * j + 1]) : "l"(xk2), "l"(w1));
                }
            }
        }

        if (lane < nvalid) {
            float* orow = out + (size_t)t * 64;
            #pragma unroll
            for (int j = 0; j < 16; j++) {
                asm volatile("st.global.v2.b64 [%0], {%1, %2};"
                             :: "l"(orow + 4 * j),
                                "l"(acc2[2 * j]), "l"(acc2[2 * j + 1])
                             : "memory");
            }
        }
    }
}

extern "C" void kernel_launch(void* const* d_in, const int* in_sizes, int n_in,
                              void* d_out, int out_size)
{
    const float* x   = (const float*)d_in[0];
    const int*   sel = (const int*)  d_in[1];
    const float* w   = (const float*)d_in[2];
    float*       out = (float*)d_out;

    cudaFuncSetAttribute(cvmm_kernel,
                         cudaFuncAttributeMaxDynamicSharedMemorySize,
                         SMEM_TOTAL);
    cvmm_kernel<<<NCTA, NTHR, SMEM_TOTAL>>>(x, sel, w, out);
}

// round 14
// speedup vs baseline: 1.2173x; 1.2173x over previous
#include <cuda_runtime.h>
#include <cstdint>
#include <cstddef>

// out[m] = x[m] @ w[sel[m]]   M=262144, K=64, N=64, E=8, fp32
//
// R13: register-block 2 tokens per lane (64-token single-expert chunks).
// Each weight LDS.128 broadcast now feeds 4 FFMA2 (2 tokens x f32x2),
// halving the dominant l1tex LDS traffic vs the T=1 version.

#define TOK_M   262144
#define NCTA    152
#define NTHR    256
#define MAXTB   1760          // ceil(262144/152)=1725, padded

#define SMEM_W_BYTES   (8 * 64 * 64 * 4)            // 131072
#define SMEM_IDX_OFF   SMEM_W_BYTES                 // u16[MAXTB] = 3520 B
#define SMEM_SEL_OFF   (SMEM_IDX_OFF + MAXTB * 2)   // u8[MAXTB]  = 1760 B
#define SMEM_META_OFF  ((SMEM_SEL_OFF + MAXTB + 15) & ~15)
#define SMEM_TOTAL     (SMEM_META_OFF + 160)

static __device__ __forceinline__ uint32_t s2u(const void* p) {
    uint32_t a;
    asm("{ .reg .u64 t; cvta.to.shared.u64 t, %1; cvt.u32.u64 %0, t; }"
        : "=r"(a) : "l"(p));
    return a;
}

__global__ void __launch_bounds__(NTHR, 1)
cvmm_kernel(const float* __restrict__ x, const int* __restrict__ sel,
            const float* __restrict__ w, float* __restrict__ out)
{
    extern __shared__ char smem[];
    float*          w_s      = (float*)smem;
    unsigned short* idx      = (unsigned short*)(smem + SMEM_IDX_OFF);
    unsigned char*  sel_s    = (unsigned char*)(smem + SMEM_SEL_OFF);
    int*            counts   = (int*)(smem + SMEM_META_OFF);
    int*            offs     = counts + 8;
    int*            cursor   = offs + 8;
    int*            chunkoff = cursor + 8;   // 9 entries

    const int tid = threadIdx.x;
    const int bid = blockIdx.x;
    const int t0 = (int)(((long long)bid       * TOK_M) / NCTA);
    const int t1 = (int)(((long long)(bid + 1) * TOK_M) / NCTA);
    const int TB = t1 - t0;

    if (tid < 8) counts[tid] = 0;

    // ---- stage all expert weights into smem (coalesced float4 copy) ----
    {
        const float4* wg = (const float4*)w;
        float4*       ws = (float4*)w_s;
        #pragma unroll
        for (int i = 0; i < (SMEM_W_BYTES / 16) / NTHR; i++)
            ws[tid + i * NTHR] = wg[tid + i * NTHR];
    }
    __syncthreads();

    // ---- histogram over experts; stage sel in smem ----
    for (int i = tid; i < TB; i += NTHR) {
        int e = sel[t0 + i] & 7;
        sel_s[i] = (unsigned char)e;
        atomicAdd(&counts[e], 1);
    }
    __syncthreads();

    // ---- exclusive scan + 64-token chunk offsets (serial, 8 entries) ----
    if (tid == 0) {
        int acc = 0, cacc = 0;
        #pragma unroll
        for (int e = 0; e < 8; e++) {
            offs[e]     = acc;
            cursor[e]   = acc;
            chunkoff[e] = cacc;
            int c = counts[e];
            acc  += c;
            cacc += (c + 63) >> 6;
        }
        chunkoff[8] = cacc;
    }
    __syncthreads();

    // ---- scatter token local indices into per-expert lists ----
    for (int i = tid; i < TB; i += NTHR) {
        int e = sel_s[i];
        int p = atomicAdd(&cursor[e], 1);
        idx[p] = (unsigned short)i;
    }
    __syncthreads();

    // ---- phase 2: each warp consumes 64-token single-expert chunks,
    //      2 tokens per lane ----
    const int nchunks = chunkoff[8];
    const int warp = tid >> 5, lane = tid & 31;
    const uint32_t wsb = s2u(w_s);

    for (int c = warp; c < nchunks; c += NTHR / 32) {
        // expert owning chunk c (monotone chunkoff; highest match wins)
        int e = 0;
        #pragma unroll
        for (int q = 1; q < 8; q++)
            if (chunkoff[q] <= c) e = q;

        const int cc   = c - chunkoff[e];
        const int cnt  = counts[e];
        const int base = cc * 64;
        const int nrem = cnt - base;             // 1..64 tokens in this chunk
        const bool v0  = lane < nrem;
        const bool v1  = lane + 32 < nrem;
        const int li0  = base + (v0 ? lane : 0);
        const int li1  = base + (v1 ? lane + 32 : 0);
        const int tg0  = t0 + (int)idx[offs[e] + li0];
        const int tg1  = t0 + (int)idx[offs[e] + li1];

        const float4* __restrict__ xr0 = (const float4*)(x + (size_t)tg0 * 64);
        const float4* __restrict__ xr1 = (const float4*)(x + (size_t)tg1 * 64);

        unsigned long long acc0[32], acc1[32];
        #pragma unroll
        for (int j = 0; j < 32; j++) { acc0[j] = 0ull; acc1[j] = 0ull; }

        const uint32_t webase = wsb + (uint32_t)e * 16384u;

        for (int kb = 0; kb < 4; kb++) {         // K in blocks of 16
            float4 a0 = xr0[kb * 4 + 0], a1 = xr0[kb * 4 + 1];
            float4 a2 = xr0[kb * 4 + 2], a3 = xr0[kb * 4 + 3];
            float4 b0 = xr1[kb * 4 + 0], b1 = xr1[kb * 4 + 1];
            float4 b2 = xr1[kb * 4 + 2], b3 = xr1[kb * 4 + 3];
            float xa[16] = { a0.x, a0.y, a0.z, a0.w, a1.x, a1.y, a1.z, a1.w,
                             a2.x, a2.y, a2.z, a2.w, a3.x, a3.y, a3.z, a3.w };
            float xb[16] = { b0.x, b0.y, b0.z, b0.w, b1.x, b1.y, b1.z, b1.w,
                             b2.x, b2.y, b2.z, b2.w, b3.x, b3.y, b3.z, b3.w };
            const uint32_t kbase = webase + (uint32_t)kb * 4096u;
            #pragma unroll
            for (int k2 = 0; k2 < 16; k2++) {
                unsigned long long xa2, xb2;
                asm("mov.b64 %0, {%1, %1};" : "=l"(xa2) : "f"(xa[k2]));
                asm("mov.b64 %0, {%1, %1};" : "=l"(xb2) : "f"(xb[k2]));
                const uint32_t a = kbase + (uint32_t)k2 * 256u;
                #pragma unroll
                for (int j = 0; j < 16; j++) {
                    unsigned long long w0, w1;
                    asm volatile("ld.shared.v2.b64 {%0, %1}, [%2];"
                                 : "=l"(w0), "=l"(w1) : "r"(a + j * 16));
                    asm("fma.rn.f32x2 %0, %1, %2, %0;"
                        : "+l"(acc0[2 * j])     : "l"(xa2), "l"(w0));
                    asm("fma.rn.f32x2 %0, %1, %2, %0;"
                        : "+l"(acc0[2 * j + 1]) : "l"(xa2), "l"(w1));
                    asm("fma.rn.f32x2 %0, %1, %2, %0;"
                        : "+l"(acc1[2 * j])     : "l"(xb2), "l"(w0));
                    asm("fma.rn.f32x2 %0, %1, %2, %0;"
                        : "+l"(acc1[2 * j + 1]) : "l"(xb2), "l"(w1));
                }
            }
        }

        if (v0) {
            float* orow = out + (size_t)tg0 * 64;
            #pragma unroll
            for (int j = 0; j < 16; j++)
                asm volatile("st.global.v2.b64 [%0], {%1, %2};"
                             :: "l"(orow + 4 * j),
                                "l"(acc0[2 * j]), "l"(acc0[2 * j + 1])
                             : "memory");
        }
        if (v1) {
            float* orow = out + (size_t)tg1 * 64;
            #pragma unroll
            for (int j = 0; j < 16; j++)
                asm volatile("st.global.v2.b64 [%0], {%1, %2};"
                             :: "l"(orow + 4 * j),
                                "l"(acc1[2 * j]), "l"(acc1[2 * j + 1])
                             : "memory");
        }
    }
}

extern "C" void kernel_launch(void* const* d_in, const int* in_sizes, int n_in,
                              void* d_out, int out_size)
{
    const float* x   = (const float*)d_in[0];
    const int*   sel = (const int*)  d_in[1];
    const float* w   = (const float*)d_in[2];
    float*       out = (float*)d_out;

    cudaFuncSetAttribute(cvmm_kernel,
                         cudaFuncAttributeMaxDynamicSharedMemorySize,
                         SMEM_TOTAL);
    cvmm_kernel<<<NCTA, NTHR, SMEM_TOTAL>>>(x, sel, w, out);
}